// round 3
// baseline (speedup 1.0000x reference)
#include <cuda_runtime.h>
#include <cuda_bf16.h>

// FAPE loss, fused single kernel. B=4, N=2048.
//   d(i,j) = Rp_i^T xp_j + (-Rt_i^T) xt_j + dt_i,  dt_i = Rt_i^T tt_i - Rp_i^T tp_i
//   out[b] = 0.1 * mean_ij min(sqrt(||d||^2 + 1e-4), 10)
//
// R2: LDS.128 j-loads (one per component per 4 j's), 4-j unroll with packed
// FFMA2 (fma.rn.f32x2), grid 512 for occupancy. Last-block finalize.

#define BB 4
#define NN 2048
#define NBI 8           // i-blocks of 256
#define NBJ 16          // j-chunks of 128
#define JCH 128
#define BLK 256
#define NBLOCKS (BB * NBI * NBJ)   // 512

__device__ float g_partials[NBLOCKS];
__device__ unsigned int g_count = 0;

typedef unsigned long long u64;

__device__ __forceinline__ u64 pack2(float x, float y) {
    u64 r; asm("mov.b64 %0, {%1,%2};" : "=l"(r) : "f"(x), "f"(y)); return r;
}
__device__ __forceinline__ void unpack2(u64 v, float& x, float& y) {
    asm("mov.b64 {%0,%1}, %2;" : "=f"(x), "=f"(y) : "l"(v));
}
__device__ __forceinline__ u64 ffma2(u64 a, u64 b, u64 c) {
    u64 d; asm("fma.rn.f32x2 %0, %1, %2, %3;" : "=l"(d) : "l"(a), "l"(b), "l"(c)); return d;
}
__device__ __forceinline__ float fsqrt_approx(float x) {
    float y; asm("sqrt.approx.f32 %0, %1;" : "=f"(y) : "f"(x)); return y;
}

__global__ void __launch_bounds__(BLK)
fape_fused(const float* __restrict__ pR, const float* __restrict__ pT,
           const float* __restrict__ pX, const float* __restrict__ tR,
           const float* __restrict__ tT, const float* __restrict__ tX,
           float* __restrict__ out) {
    __shared__ __align__(16) float sy[6][JCH];   // SoA: xp0,xp1,xp2,xt0,xt1,xt2
    __shared__ float red[BLK];

    const int bid = blockIdx.x;
    const int b  = bid >> 7;            // / (NBI*NBJ) = /128
    const int ib = (bid >> 4) & 7;
    const int jb = bid & 15;
    const int t  = threadIdx.x;

    // Stage this block's 128-j chunk of atom positions into shared (SoA).
    if (t < JCH) {
        const int j = jb * JCH + t;
        const float* xp = pX + (b * NN + j) * 3;
        const float* xt = tX + (b * NN + j) * 3;
        sy[0][t] = xp[0]; sy[1][t] = xp[1]; sy[2][t] = xp[2];
        sy[3][t] = xt[0]; sy[4][t] = xt[1]; sy[5][t] = xt[2];
    }

    // This thread's i-frame (fused prep), pre-packed {v,v}.
    u64 P[9], Q[9], DT[3];
    {
        const int idx = b * NN + ib * BLK + t;
        const float* Rp = pR + idx * 9;
        const float* Rt = tR + idx * 9;
        const float tp0 = pT[idx*3+0], tp1 = pT[idx*3+1], tp2 = pT[idx*3+2];
        const float tt0 = tT[idx*3+0], tt1 = tT[idx*3+1], tt2 = tT[idx*3+2];
#pragma unroll
        for (int o = 0; o < 3; o++) {
            const float rp0 = Rp[0*3+o], rp1 = Rp[1*3+o], rp2 = Rp[2*3+o];
            const float rt0 = Rt[0*3+o], rt1 = Rt[1*3+o], rt2 = Rt[2*3+o];
            P[o*3+0] = pack2(rp0, rp0);
            P[o*3+1] = pack2(rp1, rp1);
            P[o*3+2] = pack2(rp2, rp2);
            Q[o*3+0] = pack2(-rt0, -rt0);
            Q[o*3+1] = pack2(-rt1, -rt1);
            Q[o*3+2] = pack2(-rt2, -rt2);
            const float dt = (rt0*tt0 + rt1*tt1 + rt2*tt2)
                           - (rp0*tp0 + rp1*tp1 + rp2*tp2);
            DT[o] = pack2(dt, dt);
        }
    }
    const u64 EPS2 = pack2(1e-4f, 1e-4f);
    __syncthreads();

    float acc0 = 0.f, acc1 = 0.f, acc2 = 0.f, acc3 = 0.f;
#pragma unroll 2
    for (int j = 0; j < JCH; j += 4) {
        // One LDS.128 per component covers 4 j's = two packed u64 pairs.
        const ulonglong2 y0 = *(const ulonglong2*)&sy[0][j];
        const ulonglong2 y1 = *(const ulonglong2*)&sy[1][j];
        const ulonglong2 y2 = *(const ulonglong2*)&sy[2][j];
        const ulonglong2 y3 = *(const ulonglong2*)&sy[3][j];
        const ulonglong2 y4 = *(const ulonglong2*)&sy[4][j];
        const ulonglong2 y5 = *(const ulonglong2*)&sy[5][j];

        // Pair A = (j, j+1)
        u64 dA0 = ffma2(P[0], y0.x, ffma2(P[1], y1.x, ffma2(P[2], y2.x,
                  ffma2(Q[0], y3.x, ffma2(Q[1], y4.x, ffma2(Q[2], y5.x, DT[0]))))));
        u64 dA1 = ffma2(P[3], y0.x, ffma2(P[4], y1.x, ffma2(P[5], y2.x,
                  ffma2(Q[3], y3.x, ffma2(Q[4], y4.x, ffma2(Q[5], y5.x, DT[1]))))));
        u64 dA2 = ffma2(P[6], y0.x, ffma2(P[7], y1.x, ffma2(P[8], y2.x,
                  ffma2(Q[6], y3.x, ffma2(Q[7], y4.x, ffma2(Q[8], y5.x, DT[2]))))));
        // Pair B = (j+2, j+3)
        u64 dB0 = ffma2(P[0], y0.y, ffma2(P[1], y1.y, ffma2(P[2], y2.y,
                  ffma2(Q[0], y3.y, ffma2(Q[1], y4.y, ffma2(Q[2], y5.y, DT[0]))))));
        u64 dB1 = ffma2(P[3], y0.y, ffma2(P[4], y1.y, ffma2(P[5], y2.y,
                  ffma2(Q[3], y3.y, ffma2(Q[4], y4.y, ffma2(Q[5], y5.y, DT[1]))))));
        u64 dB2 = ffma2(P[6], y0.y, ffma2(P[7], y1.y, ffma2(P[8], y2.y,
                  ffma2(Q[6], y3.y, ffma2(Q[7], y4.y, ffma2(Q[8], y5.y, DT[2]))))));

        u64 s2A = ffma2(dA0, dA0, ffma2(dA1, dA1, ffma2(dA2, dA2, EPS2)));
        u64 s2B = ffma2(dB0, dB0, ffma2(dB1, dB1, ffma2(dB2, dB2, EPS2)));

        float a0, a1, b0, b1;
        unpack2(s2A, a0, a1);
        unpack2(s2B, b0, b1);
        // min(sqrt(x+eps), 10) == sqrt(min(x+eps, 100))
        acc0 += fsqrt_approx(fminf(a0, 100.0f));
        acc1 += fsqrt_approx(fminf(a1, 100.0f));
        acc2 += fsqrt_approx(fminf(b0, 100.0f));
        acc3 += fsqrt_approx(fminf(b1, 100.0f));
    }

    // Deterministic block tree reduction.
    red[t] = (acc0 + acc1) + (acc2 + acc3);
    __syncthreads();
#pragma unroll
    for (int stride = BLK / 2; stride >= 1; stride >>= 1) {
        if (t < stride) red[t] += red[t + stride];
        __syncthreads();
    }

    if (t == 0) {
        g_partials[bid] = red[0];
        __threadfence();
        const unsigned r = atomicAdd(&g_count, 1);
        if (r == NBLOCKS - 1) {
            // Last block: fixed-order final sum (deterministic).
#pragma unroll
            for (int bb = 0; bb < BB; bb++) {
                float s = 0.f;
                for (int k = 0; k < NBI * NBJ; k++)
                    s += __ldcg(&g_partials[bb * (NBI * NBJ) + k]);
                out[bb] = s * (1.0f / (10.0f * (float)NN * (float)NN));
            }
            g_count = 0;   // reset for next graph replay
        }
    }
}

extern "C" void kernel_launch(void* const* d_in, const int* in_sizes, int n_in,
                              void* d_out, int out_size) {
    const float* pR = (const float*)d_in[0];  // predicted_rotations   [B,N,3,3]
    const float* pT = (const float*)d_in[1];  // predicted_translations[B,N,3]
    const float* pX = (const float*)d_in[2];  // predicted_atom_positions
    const float* tR = (const float*)d_in[3];  // true_rotations
    const float* tT = (const float*)d_in[4];  // true_translations
    const float* tX = (const float*)d_in[5];  // true_atom_positions

    fape_fused<<<NBLOCKS, BLK>>>(pR, pT, pX, tR, tT, tX, (float*)d_out);
}

// round 4
// speedup vs baseline: 1.4448x; 1.4448x over previous
#include <cuda_runtime.h>
#include <cuda_bf16.h>

// FAPE loss, fused single kernel. B=4, N=2048.
//   d(i,j) = Rp_i^T xp_j + (-Rt_i^T) xt_j + dt_i,  dt_i = Rt_i^T tt_i - Rp_i^T tp_i
//   out[b] = 0.1 * mean_ij min(sqrt(||d||^2 + 1e-4), 10)
//
// R3 = R1 inner loop (LDS.64 -> fma.rn.f32x2, clean SASS) + R2 grid (512
// blocks for occupancy) + shuffle-based block reduction. The R2 LDS.128/
// ulonglong2 packing is reverted: it forced register-pair repair MOVs on the
// fma pipe (+67% fma-pipe work).

#define BB 4
#define NN 2048
#define NBI 8           // i-blocks of 256
#define NBJ 16          // j-chunks of 128
#define JCH 128
#define BLK 256
#define NBLOCKS (BB * NBI * NBJ)   // 512

__device__ float g_partials[NBLOCKS];
__device__ unsigned int g_count = 0;

typedef unsigned long long u64;

__device__ __forceinline__ u64 pack2(float x, float y) {
    u64 r; asm("mov.b64 %0, {%1,%2};" : "=l"(r) : "f"(x), "f"(y)); return r;
}
__device__ __forceinline__ void unpack2(u64 v, float& x, float& y) {
    asm("mov.b64 {%0,%1}, %2;" : "=f"(x), "=f"(y) : "l"(v));
}
__device__ __forceinline__ u64 ffma2(u64 a, u64 b, u64 c) {
    u64 d; asm("fma.rn.f32x2 %0, %1, %2, %3;" : "=l"(d) : "l"(a), "l"(b), "l"(c)); return d;
}
__device__ __forceinline__ float fsqrt_approx(float x) {
    float y; asm("sqrt.approx.f32 %0, %1;" : "=f"(y) : "f"(x)); return y;
}

__global__ void __launch_bounds__(BLK)
fape_fused(const float* __restrict__ pR, const float* __restrict__ pT,
           const float* __restrict__ pX, const float* __restrict__ tR,
           const float* __restrict__ tT, const float* __restrict__ tX,
           float* __restrict__ out) {
    __shared__ __align__(8) float sy[6][JCH];   // SoA: xp0,xp1,xp2,xt0,xt1,xt2
    __shared__ float swred[BLK / 32];

    const int bid = blockIdx.x;
    const int b  = bid >> 7;            // / (NBI*NBJ) = /128
    const int ib = (bid >> 4) & 7;
    const int jb = bid & 15;
    const int t  = threadIdx.x;

    // Stage this block's 128-j chunk of atom positions into shared (SoA).
    if (t < JCH) {
        const int j = jb * JCH + t;
        const float* xp = pX + (b * NN + j) * 3;
        const float* xt = tX + (b * NN + j) * 3;
        sy[0][t] = xp[0]; sy[1][t] = xp[1]; sy[2][t] = xp[2];
        sy[3][t] = xt[0]; sy[4][t] = xt[1]; sy[5][t] = xt[2];
    }

    // This thread's i-frame (fused prep), pre-packed {v,v}.
    u64 P[9], Q[9], DT[3];
    {
        const int idx = b * NN + ib * BLK + t;
        const float* Rp = pR + idx * 9;
        const float* Rt = tR + idx * 9;
        const float tp0 = pT[idx*3+0], tp1 = pT[idx*3+1], tp2 = pT[idx*3+2];
        const float tt0 = tT[idx*3+0], tt1 = tT[idx*3+1], tt2 = tT[idx*3+2];
#pragma unroll
        for (int o = 0; o < 3; o++) {
            const float rp0 = Rp[0*3+o], rp1 = Rp[1*3+o], rp2 = Rp[2*3+o];
            const float rt0 = Rt[0*3+o], rt1 = Rt[1*3+o], rt2 = Rt[2*3+o];
            P[o*3+0] = pack2(rp0, rp0);
            P[o*3+1] = pack2(rp1, rp1);
            P[o*3+2] = pack2(rp2, rp2);
            Q[o*3+0] = pack2(-rt0, -rt0);
            Q[o*3+1] = pack2(-rt1, -rt1);
            Q[o*3+2] = pack2(-rt2, -rt2);
            const float dt = (rt0*tt0 + rt1*tt1 + rt2*tt2)
                           - (rp0*tp0 + rp1*tp1 + rp2*tp2);
            DT[o] = pack2(dt, dt);
        }
    }
    const u64 EPS2 = pack2(1e-4f, 1e-4f);
    __syncthreads();

    float acc0 = 0.f, acc1 = 0.f;
#pragma unroll 4
    for (int j = 0; j < JCH; j += 2) {
        // Warp-uniform LDS.64: packed pair {y_j, y_{j+1}} per component.
        const u64 y0 = *(const u64*)&sy[0][j];
        const u64 y1 = *(const u64*)&sy[1][j];
        const u64 y2 = *(const u64*)&sy[2][j];
        const u64 y3 = *(const u64*)&sy[3][j];
        const u64 y4 = *(const u64*)&sy[4][j];
        const u64 y5 = *(const u64*)&sy[5][j];

        u64 d0 = ffma2(P[0], y0, ffma2(P[1], y1, ffma2(P[2], y2,
                 ffma2(Q[0], y3, ffma2(Q[1], y4, ffma2(Q[2], y5, DT[0]))))));
        u64 d1 = ffma2(P[3], y0, ffma2(P[4], y1, ffma2(P[5], y2,
                 ffma2(Q[3], y3, ffma2(Q[4], y4, ffma2(Q[5], y5, DT[1]))))));
        u64 d2 = ffma2(P[6], y0, ffma2(P[7], y1, ffma2(P[8], y2,
                 ffma2(Q[6], y3, ffma2(Q[7], y4, ffma2(Q[8], y5, DT[2]))))));

        u64 s2 = ffma2(d0, d0, ffma2(d1, d1, ffma2(d2, d2, EPS2)));
        float lo, hi;
        unpack2(s2, lo, hi);
        // min(sqrt(x+eps), 10) == sqrt(min(x+eps, 100))
        acc0 += fsqrt_approx(fminf(lo, 100.0f));
        acc1 += fsqrt_approx(fminf(hi, 100.0f));
    }

    // Deterministic reduction: fixed butterfly within warp, then cross-warp.
    float v = acc0 + acc1;
#pragma unroll
    for (int m = 16; m >= 1; m >>= 1)
        v += __shfl_xor_sync(0xffffffffu, v, m);
    if ((t & 31) == 0) swred[t >> 5] = v;
    __syncthreads();
    if (t < 32) {
        float w = (t < BLK / 32) ? swred[t] : 0.f;
#pragma unroll
        for (int m = 4; m >= 1; m >>= 1)
            w += __shfl_xor_sync(0xffffffffu, w, m);
        if (t == 0) {
            g_partials[bid] = w;
            __threadfence();
            const unsigned r = atomicAdd(&g_count, 1);
            if (r == NBLOCKS - 1) {
                // Last block: fixed-order final sum (deterministic).
#pragma unroll
                for (int bb = 0; bb < BB; bb++) {
                    float s = 0.f;
                    for (int k = 0; k < NBI * NBJ; k++)
                        s += __ldcg(&g_partials[bb * (NBI * NBJ) + k]);
                    out[bb] = s * (1.0f / (10.0f * (float)NN * (float)NN));
                }
                g_count = 0;   // reset for next graph replay
            }
        }
    }
}

extern "C" void kernel_launch(void* const* d_in, const int* in_sizes, int n_in,
                              void* d_out, int out_size) {
    const float* pR = (const float*)d_in[0];  // predicted_rotations   [B,N,3,3]
    const float* pT = (const float*)d_in[1];  // predicted_translations[B,N,3]
    const float* pX = (const float*)d_in[2];  // predicted_atom_positions
    const float* tR = (const float*)d_in[3];  // true_rotations
    const float* tT = (const float*)d_in[4];  // true_translations
    const float* tX = (const float*)d_in[5];  // true_atom_positions

    fape_fused<<<NBLOCKS, BLK>>>(pR, pT, pX, tR, tT, tX, (float*)d_out);
}

// round 5
// speedup vs baseline: 1.5558x; 1.0768x over previous
#include <cuda_runtime.h>
#include <cuda_bf16.h>

// FAPE loss, fused single kernel. B=4, N=2048.
//   d(i,j) = Rp_i^T xp_j + (-Rt_i^T) xt_j + dt_i,  dt_i = Rt_i^T tt_i - Rp_i^T tp_i
//   out[b] = 0.1 * mean_ij min(sqrt(||d||^2 + 1e-4), 10)
//
// R4: R1 shape (grid 256, JCH 256) + 128-reg budget (launch_bounds 256,2) +
// software-pipelined y-loads (double buffer, hides LDS 29cyc) + coalesced
// frame staging through shared (kills scattered stride-9 LDGs in prep).

#define BB 4
#define NN 2048
#define NBI 8           // i-blocks of 256
#define NBJ 8           // j-chunks of 256
#define JCH 256
#define BLK 256
#define NBLOCKS (BB * NBI * NBJ)   // 256

__device__ float g_partials[NBLOCKS];
__device__ unsigned int g_count = 0;

typedef unsigned long long u64;

__device__ __forceinline__ u64 pack2(float x, float y) {
    u64 r; asm("mov.b64 %0, {%1,%2};" : "=l"(r) : "f"(x), "f"(y)); return r;
}
__device__ __forceinline__ void unpack2(u64 v, float& x, float& y) {
    asm("mov.b64 {%0,%1}, %2;" : "=f"(x), "=f"(y) : "l"(v));
}
__device__ __forceinline__ u64 ffma2(u64 a, u64 b, u64 c) {
    u64 d; asm("fma.rn.f32x2 %0, %1, %2, %3;" : "=l"(d) : "l"(a), "l"(b), "l"(c)); return d;
}
__device__ __forceinline__ float fsqrt_approx(float x) {
    float y; asm("sqrt.approx.f32 %0, %1;" : "=f"(y) : "f"(x)); return y;
}

__global__ void __launch_bounds__(BLK, 2)
fape_fused(const float* __restrict__ pR, const float* __restrict__ pT,
           const float* __restrict__ pX, const float* __restrict__ tR,
           const float* __restrict__ tT, const float* __restrict__ tX,
           float* __restrict__ out) {
    __shared__ __align__(8) float sy[6][JCH];    // SoA j-data: xp0..2, xt0..2
    __shared__ float sRp[BLK * 9];
    __shared__ float sRt[BLK * 9];
    __shared__ float sTp[BLK * 3];
    __shared__ float sTt[BLK * 3];
    __shared__ float swred[BLK / 32];

    const int bid = blockIdx.x;
    const int b  = bid >> 6;            // / (NBI*NBJ)
    const int ib = (bid >> 3) & 7;
    const int jb = bid & 7;
    const int t  = threadIdx.x;

    // ---- Coalesced staging of this block's frames + j-chunk ----
    {
        const float* baseRp = pR + (b * NN + ib * BLK) * 9;
        const float* baseRt = tR + (b * NN + ib * BLK) * 9;
        const float* baseTp = pT + (b * NN + ib * BLK) * 3;
        const float* baseTt = tT + (b * NN + ib * BLK) * 3;
#pragma unroll
        for (int k = t; k < BLK * 9; k += BLK) { sRp[k] = baseRp[k]; sRt[k] = baseRt[k]; }
#pragma unroll
        for (int k = t; k < BLK * 3; k += BLK) { sTp[k] = baseTp[k]; sTt[k] = baseTt[k]; }

        const int j = jb * JCH + t;
        const float* xp = pX + (b * NN + j) * 3;
        const float* xt = tX + (b * NN + j) * 3;
        sy[0][t] = xp[0]; sy[1][t] = xp[1]; sy[2][t] = xp[2];
        sy[3][t] = xt[0]; sy[4][t] = xt[1]; sy[5][t] = xt[2];
    }
    __syncthreads();

    // ---- Build this thread's packed i-frame from shared ----
    u64 P[9], Q[9], DT[3];
    {
        const float* Rp = sRp + t * 9;
        const float* Rt = sRt + t * 9;
        const float tp0 = sTp[t*3+0], tp1 = sTp[t*3+1], tp2 = sTp[t*3+2];
        const float tt0 = sTt[t*3+0], tt1 = sTt[t*3+1], tt2 = sTt[t*3+2];
#pragma unroll
        for (int o = 0; o < 3; o++) {
            const float rp0 = Rp[0*3+o], rp1 = Rp[1*3+o], rp2 = Rp[2*3+o];
            const float rt0 = Rt[0*3+o], rt1 = Rt[1*3+o], rt2 = Rt[2*3+o];
            P[o*3+0] = pack2(rp0, rp0);
            P[o*3+1] = pack2(rp1, rp1);
            P[o*3+2] = pack2(rp2, rp2);
            Q[o*3+0] = pack2(-rt0, -rt0);
            Q[o*3+1] = pack2(-rt1, -rt1);
            Q[o*3+2] = pack2(-rt2, -rt2);
            const float dt = (rt0*tt0 + rt1*tt1 + rt2*tt2)
                           - (rp0*tp0 + rp1*tp1 + rp2*tp2);
            DT[o] = pack2(dt, dt);
        }
    }
    const u64 EPS2 = pack2(1e-4f, 1e-4f);

    // ---- Main loop: software-pipelined (double-buffered y loads) ----
    float acc0 = 0.f, acc1 = 0.f, acc2 = 0.f, acc3 = 0.f;

    u64 ya0 = *(const u64*)&sy[0][0];
    u64 ya1 = *(const u64*)&sy[1][0];
    u64 ya2 = *(const u64*)&sy[2][0];
    u64 ya3 = *(const u64*)&sy[3][0];
    u64 ya4 = *(const u64*)&sy[4][0];
    u64 ya5 = *(const u64*)&sy[5][0];

#pragma unroll 4
    for (int j = 0; j < JCH; j += 2) {
        // Prefetch next pair (wraps harmlessly to j=0 on last iteration).
        const int jn = (j + 2) & (JCH - 1);
        const u64 yb0 = *(const u64*)&sy[0][jn];
        const u64 yb1 = *(const u64*)&sy[1][jn];
        const u64 yb2 = *(const u64*)&sy[2][jn];
        const u64 yb3 = *(const u64*)&sy[3][jn];
        const u64 yb4 = *(const u64*)&sy[4][jn];
        const u64 yb5 = *(const u64*)&sy[5][jn];

        u64 d0 = ffma2(P[0], ya0, ffma2(P[1], ya1, ffma2(P[2], ya2,
                 ffma2(Q[0], ya3, ffma2(Q[1], ya4, ffma2(Q[2], ya5, DT[0]))))));
        u64 d1 = ffma2(P[3], ya0, ffma2(P[4], ya1, ffma2(P[5], ya2,
                 ffma2(Q[3], ya3, ffma2(Q[4], ya4, ffma2(Q[5], ya5, DT[1]))))));
        u64 d2 = ffma2(P[6], ya0, ffma2(P[7], ya1, ffma2(P[8], ya2,
                 ffma2(Q[6], ya3, ffma2(Q[7], ya4, ffma2(Q[8], ya5, DT[2]))))));

        u64 s2 = ffma2(d0, d0, ffma2(d1, d1, ffma2(d2, d2, EPS2)));
        float lo, hi;
        unpack2(s2, lo, hi);
        // min(sqrt(x+eps), 10) == sqrt(min(x+eps, 100))
        if (j & 2) { acc2 += fsqrt_approx(fminf(lo, 100.0f));
                     acc3 += fsqrt_approx(fminf(hi, 100.0f)); }
        else       { acc0 += fsqrt_approx(fminf(lo, 100.0f));
                     acc1 += fsqrt_approx(fminf(hi, 100.0f)); }

        ya0 = yb0; ya1 = yb1; ya2 = yb2; ya3 = yb3; ya4 = yb4; ya5 = yb5;
    }

    // ---- Deterministic reduction: warp butterfly + cross-warp ----
    float v = (acc0 + acc1) + (acc2 + acc3);
#pragma unroll
    for (int m = 16; m >= 1; m >>= 1)
        v += __shfl_xor_sync(0xffffffffu, v, m);
    if ((t & 31) == 0) swred[t >> 5] = v;
    __syncthreads();
    if (t < 32) {
        float w = (t < BLK / 32) ? swred[t] : 0.f;
#pragma unroll
        for (int m = 4; m >= 1; m >>= 1)
            w += __shfl_xor_sync(0xffffffffu, w, m);
        if (t == 0) {
            g_partials[bid] = w;
            __threadfence();
            const unsigned r = atomicAdd(&g_count, 1);
            if (r == NBLOCKS - 1) {
                // Last block: fixed-order final sum (deterministic).
#pragma unroll
                for (int bb = 0; bb < BB; bb++) {
                    float s = 0.f;
                    for (int k = 0; k < NBI * NBJ; k++)
                        s += __ldcg(&g_partials[bb * (NBI * NBJ) + k]);
                    out[bb] = s * (1.0f / (10.0f * (float)NN * (float)NN));
                }
                g_count = 0;   // reset for next graph replay
            }
        }
    }
}

extern "C" void kernel_launch(void* const* d_in, const int* in_sizes, int n_in,
                              void* d_out, int out_size) {
    const float* pR = (const float*)d_in[0];  // predicted_rotations   [B,N,3,3]
    const float* pT = (const float*)d_in[1];  // predicted_translations[B,N,3]
    const float* pX = (const float*)d_in[2];  // predicted_atom_positions
    const float* tR = (const float*)d_in[3];  // true_rotations
    const float* tT = (const float*)d_in[4];  // true_translations
    const float* tX = (const float*)d_in[5];  // true_atom_positions

    fape_fused<<<NBLOCKS, BLK>>>(pR, pT, pX, tR, tT, tX, (float*)d_out);
}